// round 12
// baseline (speedup 1.0000x reference)
#include <cuda_runtime.h>
#include <cuda_fp16.h>
#include <cstdint>

#define NNODES 100000
#define DIM    128

// ---------------- scratch (static __device__, no runtime alloc) ----------------
__device__ __half g_lnH[NNODES * DIM];  // normalized x (no affine), fp16
__device__ __half g_AH [NNODES * DIM];  // mean agg fwd, fp16
__device__ __half g_ArH[NNODES * DIM];  // mean agg rev, fp16
__device__ float  g_din [NNODES];       // in-degree  (raw count)
__device__ float  g_dout[NNODES];       // out-degree (raw count)

// ---------------- helpers ----------------
__device__ __forceinline__ void mma_f16(float* c, const uint32_t* a, const uint32_t* b) {
    asm volatile(
        "mma.sync.aligned.m16n8k16.row.col.f32.f16.f16.f32 "
        "{%0,%1,%2,%3}, {%4,%5,%6,%7}, {%8,%9}, {%0,%1,%2,%3};\n"
        : "+f"(c[0]), "+f"(c[1]), "+f"(c[2]), "+f"(c[3])
        : "r"(a[0]), "r"(a[1]), "r"(a[2]), "r"(a[3]), "r"(b[0]), "r"(b[1]));
}

#define LDSM4(R, ADDR) \
    asm volatile("ldmatrix.sync.aligned.m8n8.x4.shared.b16 {%0,%1,%2,%3}, [%4];" \
                 : "=r"((R)[0]), "=r"((R)[1]), "=r"((R)[2]), "=r"((R)[3]) : "r"(ADDR))

__device__ __forceinline__ uint32_t h2u(__half2 h) {
    return *reinterpret_cast<uint32_t*>(&h);
}

// ---------------- kernel 1: layernorm-normalize (fp16 out) + zero accumulators ----------------
__global__ void ln_kernel(const float* __restrict__ x, int nrows) {
    int warp = (blockIdx.x * blockDim.x + threadIdx.x) >> 5;
    int lane = threadIdx.x & 31;
    if (warp >= nrows) return;
    const float4* x4 = reinterpret_cast<const float4*>(x);
    float4 v = x4[warp * 32 + lane];
    float s = v.x + v.y + v.z + v.w;
    #pragma unroll
    for (int o = 16; o > 0; o >>= 1) s += __shfl_xor_sync(0xffffffffu, s, o);
    float mu = s * (1.0f / 128.0f);
    float4 d = make_float4(v.x - mu, v.y - mu, v.z - mu, v.w - mu);
    float ss = d.x*d.x + d.y*d.y + d.z*d.z + d.w*d.w;
    #pragma unroll
    for (int o = 16; o > 0; o >>= 1) ss += __shfl_xor_sync(0xffffffffu, ss, o);
    float rs = rsqrtf(ss * (1.0f / 128.0f) + 1e-5f);
    uint2 o2;
    o2.x = h2u(__floats2half2_rn(d.x * rs, d.y * rs));
    o2.y = h2u(__floats2half2_rn(d.z * rs, d.w * rs));
    reinterpret_cast<uint2*>(g_lnH)[warp * 32 + lane] = o2;
    uint2 z = make_uint2(0u, 0u);
    reinterpret_cast<uint2*>(g_AH )[warp * 32 + lane] = z;
    reinterpret_cast<uint2*>(g_ArH)[warp * 32 + lane] = z;
    if (lane == 0) { g_din[warp] = 0.f; g_dout[warp] = 0.f; }
}

// ---------------- kernel 2a: degree count ----------------
__global__ void deg_kernel(const int* __restrict__ src, const int* __restrict__ dst,
                           int n_edges) {
    int e = blockIdx.x * blockDim.x + threadIdx.x;
    if (e >= n_edges) return;
    atomicAdd(&g_din [dst[e]], 1.0f);
    atomicAdd(&g_dout[src[e]], 1.0f);
}

// ---------------- kernel 2b: edge scatter (fp16, both dirs in one warp) ----------------
// lanes 0-15:  g_AH[d]  += ln[s] / din[d]    (16B per lane)
// lanes 16-31: g_ArH[s] += ln[d] / dout[s]
__global__ void scatter_kernel(const int* __restrict__ src, const int* __restrict__ dst,
                               int n_edges) {
    int e = (blockIdx.x * blockDim.x + threadIdx.x) >> 5;
    int lane = threadIdx.x & 31;
    if (e >= n_edges) return;
    int s = src[e];
    int d = dst[e];
    int rev = lane >> 4;            // 0 fwd, 1 rev
    int c   = lane & 15;            // 16B chunk index within the 256B row
    int nld = rev ? d : s;          // node to read ln from
    int nst = rev ? s : d;          // node accumulator to update
    float cntv = rev ? g_dout[s] : g_din[d];    // >= 1 by construction
    __half2 sc = __float2half2_rn(__frcp_rn(cntv));

    uint4 v = reinterpret_cast<const uint4*>(g_lnH)[nld * 16 + c];
    __half2* h = reinterpret_cast<__half2*>(&v);
    h[0] = __hmul2(h[0], sc);
    h[1] = __hmul2(h[1], sc);
    h[2] = __hmul2(h[2], sc);
    h[3] = __hmul2(h[3], sc);

    __half* base = rev ? g_ArH : g_AH;
    __half* p = base + nst * DIM + c * 8;
    asm volatile("red.global.add.noftz.v4.f16x2 [%0], {%1,%2,%3,%4};"
                 :: "l"(p), "r"(v.x), "r"(v.y), "r"(v.z), "r"(v.w) : "memory");
}

// ---------------- kernel 3: persistent fused SAGE GEMM (fp16 mma, fp32 acc) ----------------
// 256 threads, 2 CTAs/SM (barrier stalls overlap across CTAs). Block tile
// 128x128, 8 warps (4m x 2n), warp tile 32x64. K=256 = [ln | agg].
// Weights (gamma folded) staged in fp16 smem once per CTA; beta folded to bias.
//   out[r,:] = addsrc[r,:] + relu(acc + (b + Wself@beta) + mask[r]*(Wneigh@beta))
#define GTPB   256
#define MTILE  128
#define SB_H   264            // halves: 256 + 8 pad (conflict-free B loads)
#define SA_H   40             // halves: 32 + 8 pad  (conflict-free ldmatrix)
#define SB_BYTES (128 * SB_H * 2)             // 67584
#define SA_BYTES (MTILE * SA_H * 2)           // 10240
#define GEMM_SMEM (SB_BYTES + 2 * SA_BYTES + 256 * 4)   // 89088

__global__ __launch_bounds__(GTPB, 2) void gemm_kernel(
    const float* __restrict__ gamma, const float* __restrict__ beta,
    const float* __restrict__ Wself, const float* __restrict__ Wneigh,
    const float* __restrict__ bias,
    const float* __restrict__ addsrc, float* __restrict__ out,
    int nrows, int dir)
{
    extern __shared__ char smem[];
    __half* sBh   = reinterpret_cast<__half*>(smem);
    __half* sA0h  = reinterpret_cast<__half*>(smem + SB_BYTES);
    __half* sA1h  = reinterpret_cast<__half*>(smem + SB_BYTES + SA_BYTES);
    float*  sbias = reinterpret_cast<float*>(smem + SB_BYTES + 2 * SA_BYTES);
    float*  scn   = sbias + 128;

    const float* deg  = dir ? g_dout : g_din;   // raw count (mask: >0)
    const uint4* lnv  = reinterpret_cast<const uint4*>(g_lnH);
    const uint4* aggv = reinterpret_cast<const uint4*>(dir ? g_ArH : g_AH);

    int tid  = threadIdx.x;
    int lane = tid & 31;
    int warp = tid >> 5;
    int wm = warp >> 1;          // 0..3 : 32-row slab
    int wn = warp & 1;           // 0..1 : 64-col slab
    int t = lane & 3, g = lane >> 2;

    uint32_t sA0u = (uint32_t)__cvta_generic_to_shared(sA0h);
    uint32_t sA1u = (uint32_t)__cvta_generic_to_shared(sA1h);

    // ---- stage weights once: sB[n][k] = half(W[n][k%128] * gamma[k%128]) ----
    const float4* ga4 = reinterpret_cast<const float4*>(gamma);
    #pragma unroll
    for (int half = 0; half < 2; half++) {
        const float4* W4 = reinterpret_cast<const float4*>(half ? Wneigh : Wself);
        int koff = half * 128;
        #pragma unroll
        for (int j = 0; j < 16; j++) {
            int idx = tid + j * GTPB;           // 4096 float4 per matrix
            int n = idx >> 5, c4 = idx & 31;
            float4 v  = W4[n * 32 + c4];
            float4 gm = ga4[c4];
            uint2 o;
            o.x = h2u(__floats2half2_rn(v.x * gm.x, v.y * gm.y));
            o.y = h2u(__floats2half2_rn(v.z * gm.z, v.w * gm.w));
            *reinterpret_cast<uint2*>(sBh + n * SB_H + koff + c4 * 4) = o;
        }
    }
    // ---- bias terms (fp32) ----
    if (tid < 128) {
        const float4* be4 = reinterpret_cast<const float4*>(beta);
        const float4* Ws4 = reinterpret_cast<const float4*>(Wself);
        const float4* Wn4 = reinterpret_cast<const float4*>(Wneigh);
        float cs = 0.f, cn = 0.f;
        #pragma unroll 8
        for (int k4 = 0; k4 < 32; k4++) {
            float4 bv = be4[k4];
            float4 ws = Ws4[tid * 32 + k4];
            float4 wv = Wn4[tid * 32 + k4];
            cs += bv.x*ws.x + bv.y*ws.y + bv.z*ws.z + bv.w*ws.w;
            cn += bv.x*wv.x + bv.y*wv.y + bv.z*wv.z + bv.w*wv.w;
        }
        sbias[tid] = bias[tid] + cs;
        scn[tid]   = cn;
    }
    __syncthreads();

// chunk KC (0..7): 32 k-halves; 0-3 from ln, 4-7 from agg. 128 rows x 64B ->
// 512 x 16B cp.async, 256 threads -> 2 each.
#define ISSUE_CHUNK(KC, DSTU) do {                                             \
    const uint4* srcb = ((KC) < 4) ? lnv : aggv;                               \
    int c16 = ((KC) & 3) * 4;                                                  \
    _Pragma("unroll")                                                          \
    for (int j = 0; j < 2; j++) {                                              \
        int idx = tid + j * GTPB;                                              \
        int row = idx >> 2, c8 = idx & 3;                                      \
        int gr = row0 + row;                                                   \
        const uint4* gp = srcb + (size_t)gr * 16 + c16 + c8;                   \
        uint32_t da = (DSTU) + row * (SA_H * 2) + c8 * 16;                     \
        int sz = (gr < nrows) ? 16 : 0;                                        \
        asm volatile("cp.async.cg.shared.global [%0], [%1], 16, %2;"           \
                     :: "r"(da), "l"(gp), "r"(sz));                            \
    }                                                                          \
} while (0)

#define MMA_CHUNK(CURU) do {                                                   \
    _Pragma("unroll")                                                          \
    for (int ks = 0; ks < 2; ks++) {                                           \
        uint32_t af[2][4];                                                     \
        _Pragma("unroll")                                                      \
        for (int mi = 0; mi < 2; mi++) {                                       \
            uint32_t ad = (CURU) +                                             \
                ((wm * 32 + mi * 16 + (lane & 15)) * SA_H + ks * 16 + (lane >> 4) * 8) * 2; \
            LDSM4(af[mi], ad);                                                 \
        }                                                                      \
        uint32_t bf[8][2];                                                     \
        _Pragma("unroll")                                                      \
        for (int ni = 0; ni < 8; ni++) {                                       \
            const __half* bb = sBh + (wn * 64 + ni * 8 + g) * SB_H + kc * 32 + ks * 16 + 2 * t; \
            bf[ni][0] = *reinterpret_cast<const uint32_t*>(bb);                \
            bf[ni][1] = *reinterpret_cast<const uint32_t*>(bb + 8);            \
        }                                                                      \
        _Pragma("unroll")                                                      \
        for (int mi = 0; mi < 2; mi++)                                         \
            _Pragma("unroll")                                                  \
            for (int ni = 0; ni < 8; ni++)                                     \
                mma_f16(acc[mi][ni], af[mi], bf[ni]);                          \
    }                                                                          \
} while (0)

    int ntiles = (nrows + MTILE - 1) / MTILE;
    for (int tile = blockIdx.x; tile < ntiles; tile += gridDim.x) {
        int row0 = tile * MTILE;

        float acc[2][8][4];
        #pragma unroll
        for (int mi = 0; mi < 2; mi++)
            #pragma unroll
            for (int ni = 0; ni < 8; ni++)
                #pragma unroll
                for (int q = 0; q < 4; q++) acc[mi][ni][q] = 0.f;

        ISSUE_CHUNK(0, sA0u);
        asm volatile("cp.async.commit_group;" ::: "memory");

        #pragma unroll 1
        for (int kc = 0; kc < 8; kc++) {
            uint32_t curu = (kc & 1) ? sA1u : sA0u;
            uint32_t nxtu = (kc & 1) ? sA0u : sA1u;
            if (kc < 7) {
                ISSUE_CHUNK(kc + 1, nxtu);
                asm volatile("cp.async.commit_group;" ::: "memory");
                asm volatile("cp.async.wait_group 1;" ::: "memory");
            } else {
                asm volatile("cp.async.wait_group 0;" ::: "memory");
            }
            __syncthreads();
            MMA_CHUNK(curu);
            __syncthreads();
        }

        // ---- epilogue: out = addsrc + relu(acc + bias terms) ----
        const float2* add2 = reinterpret_cast<const float2*>(addsrc);
        float2*       out2 = reinterpret_cast<float2*>(out);
        #pragma unroll
        for (int mi = 0; mi < 2; mi++) {
            int r1 = row0 + wm * 32 + mi * 16 + g;
            int r2 = r1 + 8;
            float m1 = (r1 < nrows && deg[r1] > 0.f) ? 1.f : 0.f;
            float m2 = (r2 < nrows && deg[r2] > 0.f) ? 1.f : 0.f;
            #pragma unroll
            for (int ni = 0; ni < 8; ni++) {
                int col = wn * 64 + ni * 8 + t * 2;
                float b0 = sbias[col], b1 = sbias[col + 1];
                float c0 = scn[col],   c1 = scn[col + 1];
                if (r1 < nrows) {
                    int e = (r1 * DIM + col) >> 1;
                    float2 a = add2[e];
                    float v0 = acc[mi][ni][0] + b0 + m1 * c0;
                    float v1 = acc[mi][ni][1] + b1 + m1 * c1;
                    float2 o; o.x = a.x + fmaxf(v0, 0.f); o.y = a.y + fmaxf(v1, 0.f);
                    out2[e] = o;
                }
                if (r2 < nrows) {
                    int e = (r2 * DIM + col) >> 1;
                    float2 a = add2[e];
                    float v0 = acc[mi][ni][2] + b0 + m2 * c0;
                    float v1 = acc[mi][ni][3] + b1 + m2 * c1;
                    float2 o; o.x = a.x + fmaxf(v0, 0.f); o.y = a.y + fmaxf(v1, 0.f);
                    out2[e] = o;
                }
            }
        }
    }
#undef ISSUE_CHUNK
#undef MMA_CHUNK
}

// ---------------- launch ----------------
extern "C" void kernel_launch(void* const* d_in, const int* in_sizes, int n_in,
                              void* d_out, int out_size)
{
    const float* x       = (const float*)d_in[0];
    const int*   src     = (const int*)  d_in[1];
    const int*   dst     = (const int*)  d_in[2];
    const float* gamma   = (const float*)d_in[3];
    const float* beta    = (const float*)d_in[4];
    const float* Wself   = (const float*)d_in[5];
    const float* Wneigh  = (const float*)d_in[6];
    const float* b       = (const float*)d_in[7];
    const float* gamma_r = (const float*)d_in[8];
    const float* beta_r  = (const float*)d_in[9];
    const float* Wself_r = (const float*)d_in[10];
    const float* Wneigh_r= (const float*)d_in[11];
    const float* b_r     = (const float*)d_in[12];
    float* out = (float*)d_out;

    int N = in_sizes[0] / DIM;       // 100000
    int E = in_sizes[1];             // 640000

    // 1) normalize (fp16) + zero accumulators/degrees
    ln_kernel<<<(N + 7) / 8, 256>>>(x, N);
    // 2a) degree count
    deg_kernel<<<(E + 255) / 256, 256>>>(src, dst, E);
    // 2b) edge scatter (both directions, fp16 vector red; 1/deg via rcp)
    scatter_kernel<<<(E + 7) / 8, 256>>>(src, dst, E);
    // 3) fused GEMMs (2 CTAs/SM persistent)
    cudaFuncSetAttribute(gemm_kernel, cudaFuncAttributeMaxDynamicSharedMemorySize, GEMM_SMEM);
    int ntiles = (N + MTILE - 1) / MTILE;
    int gblocks = ntiles < 296 ? ntiles : 296;
    gemm_kernel<<<gblocks, GTPB, GEMM_SMEM>>>(gamma, beta, Wself, Wneigh, b,
                                              x, out, N, 0);
    gemm_kernel<<<gblocks, GTPB, GEMM_SMEM>>>(gamma_r, beta_r, Wself_r, Wneigh_r, b_r,
                                              out, out, N, 1);
}

// round 15
// speedup vs baseline: 1.0097x; 1.0097x over previous
#include <cuda_runtime.h>
#include <cuda_fp16.h>
#include <cstdint>

#define NNODES 100000
#define DIM    128

// ---------------- scratch (static __device__, no runtime alloc) ----------------
__device__ __half g_lnH[NNODES * DIM];  // normalized x (no affine), fp16
__device__ __half g_AH [NNODES * DIM];  // mean agg fwd, fp16
__device__ __half g_ArH[NNODES * DIM];  // mean agg rev, fp16
__device__ float  g_din [NNODES];       // in-degree  -> 1/deg (0 if deg==0)
__device__ float  g_dout[NNODES];       // out-degree -> 1/deg (0 if deg==0)

// ---------------- helpers ----------------
__device__ __forceinline__ void mma_f16(float* c, const uint32_t* a, const uint32_t* b) {
    asm volatile(
        "mma.sync.aligned.m16n8k16.row.col.f32.f16.f16.f32 "
        "{%0,%1,%2,%3}, {%4,%5,%6,%7}, {%8,%9}, {%0,%1,%2,%3};\n"
        : "+f"(c[0]), "+f"(c[1]), "+f"(c[2]), "+f"(c[3])
        : "r"(a[0]), "r"(a[1]), "r"(a[2]), "r"(a[3]), "r"(b[0]), "r"(b[1]));
}

#define LDSM4(R, ADDR) \
    asm volatile("ldmatrix.sync.aligned.m8n8.x4.shared.b16 {%0,%1,%2,%3}, [%4];" \
                 : "=r"((R)[0]), "=r"((R)[1]), "=r"((R)[2]), "=r"((R)[3]) : "r"(ADDR))

__device__ __forceinline__ uint32_t h2u(__half2 h) {
    return *reinterpret_cast<uint32_t*>(&h);
}

// ---------------- kernel 1: layernorm-normalize (fp16 out) + zero accumulators ----------------
__global__ void ln_kernel(const float* __restrict__ x, int nrows) {
    int warp = (blockIdx.x * blockDim.x + threadIdx.x) >> 5;
    int lane = threadIdx.x & 31;
    if (warp >= nrows) return;
    const float4* x4 = reinterpret_cast<const float4*>(x);
    float4 v = x4[warp * 32 + lane];
    float s = v.x + v.y + v.z + v.w;
    #pragma unroll
    for (int o = 16; o > 0; o >>= 1) s += __shfl_xor_sync(0xffffffffu, s, o);
    float mu = s * (1.0f / 128.0f);
    float4 d = make_float4(v.x - mu, v.y - mu, v.z - mu, v.w - mu);
    float ss = d.x*d.x + d.y*d.y + d.z*d.z + d.w*d.w;
    #pragma unroll
    for (int o = 16; o > 0; o >>= 1) ss += __shfl_xor_sync(0xffffffffu, ss, o);
    float rs = rsqrtf(ss * (1.0f / 128.0f) + 1e-5f);
    uint2 o2;
    o2.x = h2u(__floats2half2_rn(d.x * rs, d.y * rs));
    o2.y = h2u(__floats2half2_rn(d.z * rs, d.w * rs));
    reinterpret_cast<uint2*>(g_lnH)[warp * 32 + lane] = o2;
    uint2 z = make_uint2(0u, 0u);
    reinterpret_cast<uint2*>(g_AH )[warp * 32 + lane] = z;
    reinterpret_cast<uint2*>(g_ArH)[warp * 32 + lane] = z;
    if (lane == 0) { g_din[warp] = 0.f; g_dout[warp] = 0.f; }
}

// ---------------- kernel 2a: degree count ----------------
__global__ void deg_kernel(const int* __restrict__ src, const int* __restrict__ dst,
                           int n_edges) {
    int e = blockIdx.x * blockDim.x + threadIdx.x;
    if (e >= n_edges) return;
    atomicAdd(&g_din [dst[e]], 1.0f);
    atomicAdd(&g_dout[src[e]], 1.0f);
}

// ---------------- kernel 2b: invert degrees in place ----------------
__global__ void inv_kernel(int n_nodes) {
    int i = blockIdx.x * blockDim.x + threadIdx.x;
    if (i >= n_nodes) return;
    float a = g_din[i];
    float b = g_dout[i];
    g_din[i]  = a > 0.f ? __frcp_rn(a) : 0.f;
    g_dout[i] = b > 0.f ? __frcp_rn(b) : 0.f;
}

// ---------------- kernel 2c: edge scatter (fp16, both dirs in one warp) ----------------
// lanes 0-15:  g_AH[d]  += ln[s]*inv_din[d]   (16B per lane)
// lanes 16-31: g_ArH[s] += ln[d]*inv_dout[s]
__global__ void scatter_kernel(const int* __restrict__ src, const int* __restrict__ dst,
                               int n_edges) {
    int e = (blockIdx.x * blockDim.x + threadIdx.x) >> 5;
    int lane = threadIdx.x & 31;
    if (e >= n_edges) return;
    int s = src[e];
    int d = dst[e];
    int rev = lane >> 4;            // 0 fwd, 1 rev
    int c   = lane & 15;            // 16B chunk index within the 256B row
    int nld = rev ? d : s;          // node to read ln from
    int nst = rev ? s : d;          // node accumulator to update
    float inv = rev ? g_dout[s] : g_din[d];     // warp-group broadcast
    __half2 sc = __float2half2_rn(inv);

    uint4 v = reinterpret_cast<const uint4*>(g_lnH)[nld * 16 + c];
    __half2* h = reinterpret_cast<__half2*>(&v);
    h[0] = __hmul2(h[0], sc);
    h[1] = __hmul2(h[1], sc);
    h[2] = __hmul2(h[2], sc);
    h[3] = __hmul2(h[3], sc);

    __half* base = rev ? g_ArH : g_AH;
    __half* p = base + nst * DIM + c * 8;
    asm volatile("red.global.add.noftz.v4.f16x2 [%0], {%1,%2,%3,%4};"
                 :: "l"(p), "r"(v.x), "r"(v.y), "r"(v.z), "r"(v.w) : "memory");
}

// ---------------- kernel 3: persistent fused SAGE GEMM (fp16 mma, fp32 acc) ----------------
// Block tile 256x128, 16 warps, warp tile 32x64. K=256 = [ln | agg] (agg holds mean).
// Weights (gamma folded) staged in fp16 smem once; beta folded to bias terms.
//   out[r,:] = addsrc[r,:] + relu(acc + (b + Wself@beta) + mask[r]*(Wneigh@beta))
#define GTPB   512
#define MTILE  256
#define SB_H   264            // halves: 256 + 8 pad (conflict-free B loads)
#define SA_H   40             // halves: 32 + 8 pad  (conflict-free ldmatrix)
#define SB_BYTES (128 * SB_H * 2)             // 67584
#define SA_BYTES (MTILE * SA_H * 2)           // 20480
#define GEMM_SMEM (SB_BYTES + 2 * SA_BYTES + 256 * 4)

__global__ __launch_bounds__(GTPB, 1) void gemm_kernel(
    const float* __restrict__ gamma, const float* __restrict__ beta,
    const float* __restrict__ Wself, const float* __restrict__ Wneigh,
    const float* __restrict__ bias,
    const float* __restrict__ addsrc, float* __restrict__ out,
    int nrows, int dir)
{
    extern __shared__ char smem[];
    __half* sBh   = reinterpret_cast<__half*>(smem);
    __half* sA0h  = reinterpret_cast<__half*>(smem + SB_BYTES);
    __half* sA1h  = reinterpret_cast<__half*>(smem + SB_BYTES + SA_BYTES);
    float*  sbias = reinterpret_cast<float*>(smem + SB_BYTES + 2 * SA_BYTES);
    float*  scn   = sbias + 128;

    const float* deg  = dir ? g_dout : g_din;   // holds inv (0 iff deg==0)
    const uint4* lnv  = reinterpret_cast<const uint4*>(g_lnH);
    const uint4* aggv = reinterpret_cast<const uint4*>(dir ? g_ArH : g_AH);

    int tid  = threadIdx.x;
    int lane = tid & 31;
    int warp = tid >> 5;
    int wm = warp >> 1;          // 0..7 : 32-row slab
    int wn = warp & 1;           // 0..1 : 64-col slab
    int t = lane & 3, g = lane >> 2;

    uint32_t sA0u = (uint32_t)__cvta_generic_to_shared(sA0h);
    uint32_t sA1u = (uint32_t)__cvta_generic_to_shared(sA1h);

    // ---- stage weights once: sB[n][k] = half(W[n][k%128] * gamma[k%128]) ----
    const float4* ga4 = reinterpret_cast<const float4*>(gamma);
    #pragma unroll
    for (int half = 0; half < 2; half++) {
        const float4* W4 = reinterpret_cast<const float4*>(half ? Wneigh : Wself);
        int koff = half * 128;
        #pragma unroll
        for (int j = 0; j < 8; j++) {
            int idx = tid + j * GTPB;           // 4096 float4 per matrix
            int n = idx >> 5, c4 = idx & 31;
            float4 v  = W4[n * 32 + c4];
            float4 gm = ga4[c4];
            uint2 o;
            o.x = h2u(__floats2half2_rn(v.x * gm.x, v.y * gm.y));
            o.y = h2u(__floats2half2_rn(v.z * gm.z, v.w * gm.w));
            *reinterpret_cast<uint2*>(sBh + n * SB_H + koff + c4 * 4) = o;
        }
    }
    // ---- bias terms (fp32) ----
    if (tid < 128) {
        const float4* be4 = reinterpret_cast<const float4*>(beta);
        const float4* Ws4 = reinterpret_cast<const float4*>(Wself);
        const float4* Wn4 = reinterpret_cast<const float4*>(Wneigh);
        float cs = 0.f, cn = 0.f;
        #pragma unroll 8
        for (int k4 = 0; k4 < 32; k4++) {
            float4 bv = be4[k4];
            float4 ws = Ws4[tid * 32 + k4];
            float4 wv = Wn4[tid * 32 + k4];
            cs += bv.x*ws.x + bv.y*ws.y + bv.z*ws.z + bv.w*ws.w;
            cn += bv.x*wv.x + bv.y*wv.y + bv.z*wv.z + bv.w*wv.w;
        }
        sbias[tid] = bias[tid] + cs;
        scn[tid]   = cn;
    }
    __syncthreads();

// chunk KC (0..7): 32 k-halves; 0-3 from ln, 4-7 from agg. Row = 64B -> 4 x 16B cp.async
#define ISSUE_CHUNK(KC, DSTU) do {                                             \
    const uint4* srcb = ((KC) < 4) ? lnv : aggv;                               \
    int c16 = ((KC) & 3) * 4;                                                  \
    _Pragma("unroll")                                                          \
    for (int j = 0; j < 2; j++) {                                              \
        int idx = tid + j * GTPB;                                              \
        int row = idx >> 2, c8 = idx & 3;                                      \
        int gr = row0 + row;                                                   \
        const uint4* gp = srcb + (size_t)gr * 16 + c16 + c8;                   \
        uint32_t da = (DSTU) + row * (SA_H * 2) + c8 * 16;                     \
        int sz = (gr < nrows) ? 16 : 0;                                        \
        asm volatile("cp.async.cg.shared.global [%0], [%1], 16, %2;"           \
                     :: "r"(da), "l"(gp), "r"(sz));                            \
    }                                                                          \
} while (0)

#define MMA_CHUNK(CURU) do {                                                   \
    _Pragma("unroll")                                                          \
    for (int ks = 0; ks < 2; ks++) {                                           \
        uint32_t af[2][4];                                                     \
        _Pragma("unroll")                                                      \
        for (int mi = 0; mi < 2; mi++) {                                       \
            uint32_t ad = (CURU) +                                             \
                ((wm * 32 + mi * 16 + (lane & 15)) * SA_H + ks * 16 + (lane >> 4) * 8) * 2; \
            LDSM4(af[mi], ad);                                                 \
        }                                                                      \
        uint32_t bf[8][2];                                                     \
        _Pragma("unroll")                                                      \
        for (int ni = 0; ni < 8; ni++) {                                       \
            const __half* bb = sBh + (wn * 64 + ni * 8 + g) * SB_H + kc * 32 + ks * 16 + 2 * t; \
            bf[ni][0] = *reinterpret_cast<const uint32_t*>(bb);                \
            bf[ni][1] = *reinterpret_cast<const uint32_t*>(bb + 8);            \
        }                                                                      \
        _Pragma("unroll")                                                      \
        for (int mi = 0; mi < 2; mi++)                                         \
            _Pragma("unroll")                                                  \
            for (int ni = 0; ni < 8; ni++)                                     \
                mma_f16(acc[mi][ni], af[mi], bf[ni]);                          \
    }                                                                          \
} while (0)

    int ntiles = (nrows + MTILE - 1) / MTILE;
    for (int tile = blockIdx.x; tile < ntiles; tile += gridDim.x) {
        int row0 = tile * MTILE;

        float acc[2][8][4];
        #pragma unroll
        for (int mi = 0; mi < 2; mi++)
            #pragma unroll
            for (int ni = 0; ni < 8; ni++)
                #pragma unroll
                for (int q = 0; q < 4; q++) acc[mi][ni][q] = 0.f;

        ISSUE_CHUNK(0, sA0u);
        asm volatile("cp.async.commit_group;" ::: "memory");

        #pragma unroll 1
        for (int kc = 0; kc < 8; kc++) {
            uint32_t curu = (kc & 1) ? sA1u : sA0u;
            uint32_t nxtu = (kc & 1) ? sA0u : sA1u;
            if (kc < 7) {
                ISSUE_CHUNK(kc + 1, nxtu);
                asm volatile("cp.async.commit_group;" ::: "memory");
                asm volatile("cp.async.wait_group 1;" ::: "memory");
            } else {
                asm volatile("cp.async.wait_group 0;" ::: "memory");
            }
            __syncthreads();
            MMA_CHUNK(curu);
            __syncthreads();
        }

        // ---- epilogue: out = addsrc + relu(acc + bias terms) ----
        const float2* add2 = reinterpret_cast<const float2*>(addsrc);
        float2*       out2 = reinterpret_cast<float2*>(out);
        #pragma unroll
        for (int mi = 0; mi < 2; mi++) {
            int r1 = row0 + wm * 32 + mi * 16 + g;
            int r2 = r1 + 8;
            float m1 = (r1 < nrows && deg[r1] > 0.f) ? 1.f : 0.f;
            float m2 = (r2 < nrows && deg[r2] > 0.f) ? 1.f : 0.f;
            #pragma unroll
            for (int ni = 0; ni < 8; ni++) {
                int col = wn * 64 + ni * 8 + t * 2;
                float b0 = sbias[col], b1 = sbias[col + 1];
                float c0 = scn[col],   c1 = scn[col + 1];
                if (r1 < nrows) {
                    int e = (r1 * DIM + col) >> 1;
                    float2 a = add2[e];
                    float v0 = acc[mi][ni][0] + b0 + m1 * c0;
                    float v1 = acc[mi][ni][1] + b1 + m1 * c1;
                    float2 o; o.x = a.x + fmaxf(v0, 0.f); o.y = a.y + fmaxf(v1, 0.f);
                    out2[e] = o;
                }
                if (r2 < nrows) {
                    int e = (r2 * DIM + col) >> 1;
                    float2 a = add2[e];
                    float v0 = acc[mi][ni][2] + b0 + m2 * c0;
                    float v1 = acc[mi][ni][3] + b1 + m2 * c1;
                    float2 o; o.x = a.x + fmaxf(v0, 0.f); o.y = a.y + fmaxf(v1, 0.f);
                    out2[e] = o;
                }
            }
        }
    }
#undef ISSUE_CHUNK
#undef MMA_CHUNK
}

// ---------------- launch ----------------
extern "C" void kernel_launch(void* const* d_in, const int* in_sizes, int n_in,
                              void* d_out, int out_size)
{
    const float* x       = (const float*)d_in[0];
    const int*   src     = (const int*)  d_in[1];
    const int*   dst     = (const int*)  d_in[2];
    const float* gamma   = (const float*)d_in[3];
    const float* beta    = (const float*)d_in[4];
    const float* Wself   = (const float*)d_in[5];
    const float* Wneigh  = (const float*)d_in[6];
    const float* b       = (const float*)d_in[7];
    const float* gamma_r = (const float*)d_in[8];
    const float* beta_r  = (const float*)d_in[9];
    const float* Wself_r = (const float*)d_in[10];
    const float* Wneigh_r= (const float*)d_in[11];
    const float* b_r     = (const float*)d_in[12];
    float* out = (float*)d_out;

    int N = in_sizes[0] / DIM;       // 100000
    int E = in_sizes[1];             // 640000

    // 1) normalize (fp16) + zero accumulators/degrees
    ln_kernel<<<(N + 7) / 8, 256>>>(x, N);
    // 2a) degree count (512 threads/block — launch-config only)
    deg_kernel<<<(E + 511) / 512, 512>>>(src, dst, E);
    // 2b) invert in place
    inv_kernel<<<(N + 511) / 512, 512>>>(N);
    // 2c) edge scatter (warp per edge, 16 warps/block — launch-config only)
    scatter_kernel<<<(E + 15) / 16, 512>>>(src, dst, E);
    // 3) fused GEMMs
    cudaFuncSetAttribute(gemm_kernel, cudaFuncAttributeMaxDynamicSharedMemorySize, GEMM_SMEM);
    int ntiles = (N + MTILE - 1) / MTILE;
    int gblocks = ntiles < 148 ? ntiles : 148;
    gemm_kernel<<<gblocks, GTPB, GEMM_SMEM>>>(gamma, beta, Wself, Wneigh, b,
                                              x, out, N, 0);
    gemm_kernel<<<gblocks, GTPB, GEMM_SMEM>>>(gamma_r, beta_r, Wself_r, Wneigh_r, b_r,
                                              out, out, N, 1);
}